// round 16
// baseline (speedup 1.0000x reference)
#include <cuda_runtime.h>
#include <cstdint>

// Soft Smith-Waterman, linear (exp) domain, 16x16 row-blocked wavefront
// (two stacked 8x16 passes per step), per-lane exponent renorm, batched
// acquire/release edge protocol (R14-proven). SINGLE KERNEL per launch:
// epoch derived from a global ticket counter (32 CTAs/launch), flags grow
// monotonically across graph replays, g_max double-buffered, last-finishing
// CTA writes the output and resets the next epoch's max buffer.
// Lane l owns cols 16l..16l+15 of its 512-col band; computes 16 rows x 16
// cols per step, staggered 1 step/lane. 4 bands x 8 batches = 32 CTAs.

#define MM 2048
#define NN 2048
#define RB 16
#define BANDW 512
#define NB 4
#define NROWBLK (MM / RB)          // 128
#define NSTEP (NROWBLK + 31)       // 159
#define SLACK 16
#define SMEM_BYTES (3 * RB * BANDW * 4)   // 98304
#define LN2   0.6931471805599453f
#define LOG2E 1.4426950408889634f
#define EG    0.36787944117144233f    // e^-1

__device__ float        g_edgeY[8][NB][MM];
__device__ int          g_edgeK[8][NB][NROWBLK];
__device__ int          g_flag[8][NB];      // monotonic across replays
__device__ int          g_max[2][8];        // double-buffered per epoch parity
__device__ unsigned int g_ticket;           // monotonic
__device__ unsigned int g_done;             // monotonic

static __device__ __forceinline__ float ex2f(float x) {
    float r; asm("ex2.approx.f32 %0, %1;" : "=f"(r) : "f"(x)); return r;
}
static __device__ __forceinline__ float lg2f(float x) {
    float r; asm("lg2.approx.f32 %0, %1;" : "=f"(r) : "f"(x)); return r;
}
static __device__ __forceinline__ int ld_acq(const int* p) {
    int v; asm volatile("ld.global.acquire.gpu.b32 %0, [%1];" : "=r"(v) : "l"(p)); return v;
}
static __device__ __forceinline__ void st_rel(int* p, int v) {
    asm volatile("st.global.release.gpu.b32 [%0], %1;" :: "l"(p), "r"(v) : "memory");
}
static __device__ __forceinline__ int ldcg_i(const int* p) {
    int v; asm volatile("ld.global.cg.b32 %0, [%1];" : "=r"(v) : "l"(p)); return v;
}
static __device__ __forceinline__ float4 ldcg4(const float4* p) {
    float4 v;
    asm volatile("ld.global.cg.v4.f32 {%0,%1,%2,%3}, [%4];"
                 : "=f"(v.x), "=f"(v.y), "=f"(v.z), "=f"(v.w) : "l"(p));
    return v;
}
static __device__ __forceinline__ void stcg4(float4* p, float4 v) {
    asm volatile("st.global.cg.v4.f32 [%0], {%1,%2,%3,%4};"
                 :: "l"(p), "f"(v.x), "f"(v.y), "f"(v.z), "f"(v.w) : "memory");
}
static __device__ __forceinline__ void stcg_i(int* p, int v) {
    asm volatile("st.global.cg.b32 [%0], %1;" :: "l"(p), "r"(v) : "memory");
}
static __device__ __forceinline__ void cp16(uint32_t dst, const void* src) {
    asm volatile("cp.async.cg.shared.global [%0], [%1], 16;" :: "r"(dst), "l"(src));
}
static __device__ __forceinline__ void cp_commit() {
    asm volatile("cp.async.commit_group;" ::: "memory");
}
template <int N> static __device__ __forceinline__ void cp_wait() {
    asm volatile("cp.async.wait_group %0;" :: "n"(N) : "memory");
}
static __device__ __forceinline__ float pow2i(int k) {   // 2^k, k in [-126,127]
    return __int_as_float((127 + k) << 23);
}

__global__ void __launch_bounds__(32, 1)
sw_wave_kernel(const float* __restrict__ S, float* __restrict__ out) {
    extern __shared__ float4 stile[];   // [slot3][row16][h4][lane32]

    const int b = blockIdx.y;
    const int w = blockIdx.x;
    const int l = threadIdx.x;

    // ---- epoch from global ticket (32 CTAs per launch, launches serialized) ----
    unsigned int tk = 0;
    if (l == 0) tk = atomicAdd(&g_ticket, 1u);
    const unsigned int epoch = __shfl_sync(0xffffffffu, tk, 0) >> 5;
    const int base = (int)(epoch << 8);   // flag namespace per epoch (values <= 128)

    const float* Sl = S + (size_t)b * MM * NN + (size_t)w * BANDW + (size_t)l * 16;
    const int*   flagp   = (w > 0) ? &g_flag[b][w - 1]  : (const int*)0;
    const float* edgeYp  = (w > 0) ? g_edgeY[b][w - 1]  : (const float*)0;
    const int*   edgeKp  = (w > 0) ? g_edgeK[b][w - 1]  : (const int*)0;
    float*       myedgeY = g_edgeY[b][w];
    int*         myedgeK = g_edgeK[b][w];
    int*         myflag  = &g_flag[b][w];
    const bool   produce = (w != NB - 1);
    const uint32_t smem_u32 = (uint32_t)__cvta_generic_to_shared(&stile[0]);

    float B[16];
    #pragma unroll
    for (int j = 0; j < 16; ++j) B[j] = 1.f;
    float yRa[8], yRb[8];
    #pragma unroll
    for (int j = 0; j < 8; ++j) { yRa[j] = 1.f; yRb[j] = 1.f; }
    float y15p = 1.f, ecarry = 1.f, C = 1.f;
    float Ymax = 0.f, vh = 0.f;
    int   Ki = 0;
    int   flag_seen = base;

#define ISSUE_SLOT(SS, SLOT) { \
    int r0_ = RB * ((SS) - l); \
    r0_ = max(0, min(MM - RB, r0_)); \
    const float* src_ = Sl + (size_t)r0_ * NN; \
    _Pragma("unroll") for (int rr = 0; rr < RB; ++rr) { \
        uint32_t d_ = smem_u32 + ((((SLOT) * RB + rr) * 4) * 32 + l) * 16; \
        const float* sr_ = src_ + (size_t)rr * NN; \
        cp16(d_, sr_);            cp16(d_ + 512,  sr_ + 4); \
        cp16(d_ + 1024, sr_ + 8); cp16(d_ + 1536, sr_ + 12); } \
    cp_commit(); }

// 8x16 pass: rows ROWBASE..ROWBASE+7, left column Lx (updated in place to the
// lane's col-15 values), B = bottom boundary (updated to this pass's last row),
// dc_ = initial diagonal (left neighbor, row ROWBASE-1).
// Reassociated cell: a = fmaf(EG,left,fmaf(es,diag,C)) (independent of the
// vertical chain), v = fmaf(EG, v_prev, a) -> 1 FMA (4 cy) per chain link.
#define PASS(ROWBASE, Lx, DC, VALID) { \
    float dc_ = (DC); \
    _Pragma("unroll") for (int h = 0; h < 4; ++h) { \
        float4 sq[8]; \
        _Pragma("unroll") for (int t = 0; t < 8; ++t) \
            sq[t] = stile[((sl_cur * RB + (ROWBASE) + t) * 4 + h) * 32 + l]; \
        _Pragma("unroll") for (int c2 = 0; c2 < 4; ++c2) { \
            const int cc = 4 * h + c2; \
            float u_ = B[cc]; \
            float es0 = ex2f(((const float*)&sq[0])[c2] * LOG2E); \
            float es1 = ex2f(((const float*)&sq[1])[c2] * LOG2E); \
            float es2 = ex2f(((const float*)&sq[2])[c2] * LOG2E); \
            float es3 = ex2f(((const float*)&sq[3])[c2] * LOG2E); \
            float es4 = ex2f(((const float*)&sq[4])[c2] * LOG2E); \
            float es5 = ex2f(((const float*)&sq[5])[c2] * LOG2E); \
            float es6 = ex2f(((const float*)&sq[6])[c2] * LOG2E); \
            float es7 = ex2f(((const float*)&sq[7])[c2] * LOG2E); \
            float a0 = fmaf(EG, Lx[0], fmaf(es0, dc_,   C)); \
            float a1 = fmaf(EG, Lx[1], fmaf(es1, Lx[0], C)); \
            float a2 = fmaf(EG, Lx[2], fmaf(es2, Lx[1], C)); \
            float a3 = fmaf(EG, Lx[3], fmaf(es3, Lx[2], C)); \
            float a4 = fmaf(EG, Lx[4], fmaf(es4, Lx[3], C)); \
            float a5 = fmaf(EG, Lx[5], fmaf(es5, Lx[4], C)); \
            float a6 = fmaf(EG, Lx[6], fmaf(es6, Lx[5], C)); \
            float a7 = fmaf(EG, Lx[7], fmaf(es7, Lx[6], C)); \
            float v0 = fmaf(EG, u_, a0); \
            float v1 = fmaf(EG, v0, a1); \
            float v2 = fmaf(EG, v1, a2); \
            float v3 = fmaf(EG, v2, a3); \
            float v4 = fmaf(EG, v3, a4); \
            float v5 = fmaf(EG, v4, a5); \
            float v6 = fmaf(EG, v5, a6); \
            float v7 = fmaf(EG, v6, a7); \
            dc_ = u_; \
            B[cc] = (VALID) ? v7 : u_; \
            ymx_ = fmaxf(ymx_, fmaxf(fmaxf(fmaxf(v0, v1), fmaxf(v2, v3)), \
                                     fmaxf(fmaxf(v4, v5), fmaxf(v6, v7)))); \
            Lx[0] = v0; Lx[1] = v1; Lx[2] = v2; Lx[3] = v3; \
            Lx[4] = v4; Lx[5] = v5; Lx[6] = v6; Lx[7] = v7; \
        } \
    } }

    ISSUE_SLOT(0, 0)
    ISSUE_SLOT(1, 1)

    if (w > 0) { while (flag_seen < base + SLACK) flag_seen = ld_acq(flagp); }

    int sl_cur = 0, sl_iss = 2;
    for (int sb = 0; sb < NSTEP; sb += 2) {
        // ---- per-lane renorm every 2 steps (32 rows) ----
        if (sb != 0) {
            float m_ = B[0];
            #pragma unroll
            for (int j = 1; j < 16; ++j) m_ = fmaxf(m_, B[j]);
            int k_ = (__float_as_int(m_) >> 23) - 127;   // m_ > 0 always
            float sc_ = pow2i(-k_);
            vh = fmaxf(vh, lg2f(Ymax) + (float)Ki);
            Ymax = 0.f; Ki += k_; C *= sc_;
            #pragma unroll
            for (int j = 0; j < 16; ++j) B[j] *= sc_;
            #pragma unroll
            for (int j = 0; j < 8; ++j) { yRa[j] *= sc_; yRb[j] *= sc_; }
            y15p *= sc_; ecarry *= sc_;
        }

        // ---- batched flag acquire: one per 2 steps (Ki constant in batch) ----
        const bool eb = (w > 0) && (sb < NROWBLK);
        if (eb) {
            const int need = base + min(sb + 2, NROWBLK);
            while (flag_seen < need) flag_seen = ld_acq(flagp);
        }

        #pragma unroll
        for (int j = 0; j < 2; ++j) {
            const int s = sb + j;
            if (s >= NSTEP) break;

            ISSUE_SLOT(s + 2, sl_iss)
            cp_wait<2>();

            // ---- edge intake for this step (flag already acquired) ----
            float e_[16];
            if (w > 0 && s < NROWBLK) {
                const int kg = ldcg_i(edgeKp + s);
                const float fs = pow2i(max(-126, min(127, kg - Ki)));
                const float4* yp = (const float4*)(edgeYp + RB * s);
                #pragma unroll
                for (int q = 0; q < 4; ++q) {
                    float4 yv = ldcg4(yp + q);
                    e_[4 * q]     = yv.x * fs; e_[4 * q + 1] = yv.y * fs;
                    e_[4 * q + 2] = yv.z * fs; e_[4 * q + 3] = yv.w * fs;
                }
            } else {
                #pragma unroll
                for (int t = 0; t < 16; ++t) e_[t] = C;
            }

            // ---- neighbor exchange (values from previous step) ----
            int kk_ = __shfl_up_sync(0xffffffffu, Ki, 1);
            float fs_ = pow2i(max(-126, min(127, kk_ - Ki)));
            float La[8], Lb[8], Ld;
            #pragma unroll
            for (int t = 0; t < 8; ++t) {
                float ta = __shfl_up_sync(0xffffffffu, yRa[t], 1);
                float tb = __shfl_up_sync(0xffffffffu, yRb[t], 1);
                La[t] = (l == 0) ? e_[t]     : ta * fs_;
                Lb[t] = (l == 0) ? e_[8 + t] : tb * fs_;
            }
            { float tv = __shfl_up_sync(0xffffffffu, y15p, 1);
              Ld = (l == 0) ? ecarry : tv * fs_; }
            ecarry = e_[15];

            const bool valid_ = (s >= l) && (s - l < NROWBLK);
            const bool z_ = (s == l);
            if (z_) Ld = C;
            #pragma unroll
            for (int t = 0; t < 16; ++t) if (z_) B[t] = C;

            const float dcB = La[7];     // diag for bottom pass (neighbor row 7)
            float ymx_ = 0.f;

            PASS(0, La, Ld,  valid_)     // rows 0..7
            PASS(8, Lb, dcB, valid_)     // rows 8..15

            Ymax = fmaxf(Ymax, valid_ ? ymx_ : 0.f);
            { float t15 = yRb[7];
              #pragma unroll
              for (int t = 0; t < 8; ++t) {
                  yRa[t] = valid_ ? La[t] : yRa[t];
                  yRb[t] = valid_ ? Lb[t] : yRb[t];
              }
              y15p = valid_ ? t15 : y15p; }

            // ---- publish 16-row group (lane 31) + release flag ----
            if (l == 31 && produce && valid_) {
                const int g = s - 31;
                float4* yp = (float4*)(myedgeY + RB * g);
                stcg4(yp,     make_float4(yRa[0], yRa[1], yRa[2], yRa[3]));
                stcg4(yp + 1, make_float4(yRa[4], yRa[5], yRa[6], yRa[7]));
                stcg4(yp + 2, make_float4(yRb[0], yRb[1], yRb[2], yRb[3]));
                stcg4(yp + 3, make_float4(yRb[4], yRb[5], yRb[6], yRb[7]));
                stcg_i(myedgeK + g, Ki);
                st_rel(myflag, base + g + 1);
            }

            sl_cur = (sl_cur == 2) ? 0 : sl_cur + 1;
            sl_iss = (sl_iss == 2) ? 0 : sl_iss + 1;
        }
    }

    // ---- final flush + warp reduce + publish to this epoch's max buffer ----
    vh = fmaxf(vh, lg2f(Ymax) + (float)Ki);
    float hv = vh * LN2;
    #pragma unroll
    for (int o = 16; o; o >>= 1)
        hv = fmaxf(hv, __shfl_xor_sync(0xffffffffu, hv, o));
    if (l == 0) {
        atomicMax(&g_max[epoch & 1][b], __float_as_int(fmaxf(hv, 0.f)));
        __threadfence();
        unsigned int d = atomicAdd(&g_done, 1u);
        if ((d & 31u) == 31u) {          // last CTA of this launch
            __threadfence();
            #pragma unroll
            for (int i = 0; i < 8; ++i) {
                out[i] = __int_as_float(g_max[epoch & 1][i]);
                g_max[(epoch + 1) & 1][i] = 0;   // reset next epoch's buffer
            }
        }
    }
#undef ISSUE_SLOT
#undef PASS
}

extern "C" void kernel_launch(void* const* d_in, const int* in_sizes, int n_in,
                              void* d_out, int out_size) {
    (void)n_in; (void)in_sizes; (void)out_size;
    const float* S = (const float*)d_in[0];
    float* out = (float*)d_out;

    cudaFuncSetAttribute(sw_wave_kernel,
                         cudaFuncAttributeMaxDynamicSharedMemorySize, SMEM_BYTES);
    dim3 grid(NB, 8);
    sw_wave_kernel<<<grid, 32, SMEM_BYTES>>>(S, out);
}